// round 1
// baseline (speedup 1.0000x reference)
#include <cuda_runtime.h>
#include <math.h>

#define NMAX 8192
#define Hd   512
#define Pd   32
#define Dd   64
#define Kd   100
#define CL   64          // chunk length for the parallel scan
#define NCMAX (NMAX/CL)  // 128 chunks

// ---------------- scratch (static device globals; no allocation) -------------
__device__ float  g_Vinv[Dd*Dd];
__device__ float  g_W[Dd*Hd];        // V^-1 @ B
__device__ float  g_EA[Dd*Kd];       // E @ alpha
__device__ float  g_G[Dd*Kd];        // V^-1 @ E @ alpha
__device__ float  g_y0[Dd];          // V^-1 @ x0
__device__ float2 g_e[NMAX*Pd];      // per-step complex decay  (a, c)
__device__ float2 g_u[NMAX*Pd];      // per-step complex input  q*w + g
__device__ float2 g_Ec[NCMAX*Pd];    // chunk composite multiplier
__device__ float2 g_Uc[NCMAX*Pd];    // chunk composite offset
__device__ float2 g_carry[NCMAX*Pd]; // state entering each chunk
__device__ float  g_Y[NMAX*Dd];      // y_right (diagonalized state), row-major

__device__ __forceinline__ float2 cmul(float2 a, float2 b) {
    return make_float2(a.x*b.x - a.y*b.y, a.x*b.y + a.y*b.x);
}
__device__ __forceinline__ float softplusf(float x) {
    return x > 0.f ? x + log1pf(expf(-x)) : log1pf(expf(x));
}

// ---------------- K1: 64x64 Gauss-Jordan inverse of V ------------------------
__global__ void k_inv(const float* __restrict__ V) {
    __shared__ float A[Dd][2*Dd + 1];
    __shared__ float f[Dd];
    int tid = threadIdx.x;
    for (int i = tid; i < Dd*Dd; i += blockDim.x) {
        int r = i >> 6, c = i & 63;
        A[r][c]      = V[i];
        A[r][Dd + c] = (r == c) ? 1.f : 0.f;
    }
    __syncthreads();
    for (int k = 0; k < Dd; k++) {
        float inv = 1.f / A[k][k];
        if (tid < 2*Dd) A[k][tid] *= inv;
        __syncthreads();
        if (tid < Dd) f[tid] = (tid == k) ? 0.f : A[tid][k];
        __syncthreads();
        for (int i = tid; i < Dd*2*Dd; i += blockDim.x) {
            int r = i >> 7, c = i & 127;
            if (r != k) A[r][c] -= f[r] * A[k][c];
        }
        __syncthreads();
    }
    for (int i = tid; i < Dd*Dd; i += blockDim.x) {
        int r = i >> 6, c = i & 63;
        g_Vinv[i] = A[r][Dd + c];
    }
}

// ---------------- K1b: W = Vinv @ B  (64 x 512) ------------------------------
__global__ void k_W(const float* __restrict__ B) {
    int idx = blockIdx.x * blockDim.x + threadIdx.x;
    if (idx >= Dd*Hd) return;
    int d = idx / Hd, h = idx % Hd;
    float acc = 0.f;
    #pragma unroll 16
    for (int k = 0; k < Dd; k++) acc += g_Vinv[d*Dd + k] * B[k*Hd + h];
    g_W[idx] = acc;
}

// ---------------- K1c: EA = E @ alpha (64 x 100) -----------------------------
__global__ void k_EA(const float* __restrict__ E, const float* __restrict__ alpha) {
    int idx = blockIdx.x * blockDim.x + threadIdx.x;
    if (idx >= Dd*Kd) return;
    int d = idx / Kd, kk = idx % Kd;
    float acc = 0.f;
    #pragma unroll
    for (int r = 0; r < 32; r++) acc += E[d*32 + r] * alpha[r*Kd + kk];
    g_EA[idx] = acc;
}

// ---------------- K1d: G = Vinv @ EA  + y0 = Vinv @ x0 -----------------------
__global__ void k_G(const float* __restrict__ x0) {
    int idx = blockIdx.x * blockDim.x + threadIdx.x;
    if (idx < Dd*Kd) {
        int d = idx / Kd, kk = idx % Kd;
        float acc = 0.f;
        #pragma unroll 16
        for (int j = 0; j < Dd; j++) acc += g_Vinv[d*Dd + j] * g_EA[j*Kd + kk];
        g_G[idx] = acc;
    }
    if (idx < Dd) {
        float acc = 0.f;
        #pragma unroll 16
        for (int k = 0; k < Dd; k++) acc += g_Vinv[idx*Dd + k] * x0[k];
        g_y0[idx] = acc;
    }
}

// ---------------- K2: per-step features ---------------------------------------
// GEMM (64 rows n) x (96 cols: 32 gate + 64 w) over H=512, then the per-(n,p)
// transcendental math producing complex (e, u).
__global__ void k_features(const float* __restrict__ times,
                           const int*   __restrict__ marks,
                           const float* __restrict__ U,
                           const float* __restrict__ gw,
                           const float* __restrict__ gb,
                           const float* __restrict__ llr,
                           const float* __restrict__ lim) {
    __shared__ float sm[64*65 + 96*65];   // Us tile, Ws tile (padded)
    float* Us = sm;            // [64][65]
    float* Ws = sm + 64*65;    // [96][65]
    int tid = threadIdx.x;
    int n0  = blockIdx.x * 64;
    int tx = tid & 15, ty = tid >> 4;

    float acc[4][6];
    #pragma unroll
    for (int i = 0; i < 4; i++)
        #pragma unroll
        for (int j = 0; j < 6; j++) acc[i][j] = 0.f;

    for (int h0 = 0; h0 < Hd; h0 += 64) {
        __syncthreads();
        // load 64x64 u tile (float4)
        for (int i = tid; i < 64*16; i += 256) {
            int r = i >> 4, c4 = i & 15;
            float4 v = *(const float4*)&U[(n0 + r)*Hd + h0 + c4*4];
            float* dst = &Us[r*65 + c4*4];
            dst[0] = v.x; dst[1] = v.y; dst[2] = v.z; dst[3] = v.w;
        }
        // load 96x64 weight tile: rows 0..31 gate_w, rows 32..95 W
        for (int i = tid; i < 96*16; i += 256) {
            int r = i >> 4, c4 = i & 15;
            const float* src = (r < 32) ? &gw[r*Hd + h0 + c4*4]
                                        : &g_W[(r-32)*Hd + h0 + c4*4];
            float4 v = *(const float4*)src;
            float* dst = &Ws[r*65 + c4*4];
            dst[0] = v.x; dst[1] = v.y; dst[2] = v.z; dst[3] = v.w;
        }
        __syncthreads();
        #pragma unroll 4
        for (int h = 0; h < 64; h++) {
            float rv[4], cv[6];
            #pragma unroll
            for (int ri = 0; ri < 4; ri++) rv[ri] = Us[(ty + 16*ri)*65 + h];
            #pragma unroll
            for (int ci = 0; ci < 6; ci++) cv[ci] = Ws[(tx + 16*ci)*65 + h];
            #pragma unroll
            for (int ri = 0; ri < 4; ri++)
                #pragma unroll
                for (int ci = 0; ci < 6; ci++)
                    acc[ri][ci] = fmaf(rv[ri], cv[ci], acc[ri][ci]);
        }
    }

    // stash M = [gate_pre | w] into smem (reuse), 64 x 96 with pad 97
    __syncthreads();
    float* M = sm;  // 64*97 = 6208 floats, fits
    #pragma unroll
    for (int ri = 0; ri < 4; ri++)
        #pragma unroll
        for (int ci = 0; ci < 6; ci++)
            M[(ty + 16*ri)*97 + (tx + 16*ci)] = acc[ri][ci];
    __syncthreads();

    // per (row, p) math
    for (int t = tid; t < 64*Pd; t += 256) {
        int r = t >> 5, p = t & 31;
        int n = n0 + r;
        float tn = times[n];
        float dt = tn - ((n > 0) ? times[n-1] : 0.f);
        float gate = softplusf(M[r*97 + p] + gb[p]);
        float re   = -softplusf(llr[p]) * gate;
        float im   = lim[p];
        float er = expf(re * dt);
        float th = im * dt;
        float a = er * cosf(th);
        float c = er * sinf(th);
        float denom = re*re + im*im;
        float nr = a - 1.f, ni = c;
        float qr = (nr*re + ni*im) / (denom + 1e-12f);
        float qi = (ni*re - nr*im) / (denom + 1e-12f);
        if (denom < 1e-8f) { qr = dt; qi = 0.f; }
        float wre = M[r*97 + 32 + 2*p];
        float wim = M[r*97 + 33 + 2*p];
        float pos = (dt > 0.f) ? 1.f : 0.f;
        int   mk  = marks[n];
        float ure = (qr*wre - qi*wim) * pos + g_G[(2*p)*Kd + mk];
        float uim = (qr*wim + qi*wre) * pos + g_G[(2*p+1)*Kd + mk];
        g_e[n*Pd + p] = make_float2(a, c);
        g_u[n*Pd + p] = make_float2(ure, uim);
    }
}

// ---------------- K3: per-chunk composite (E_c, U_c) -------------------------
__global__ void k_chunk() {
    int c = blockIdx.x * (blockDim.x >> 5) + (threadIdx.x >> 5);
    int p = threadIdx.x & 31;
    float2 E = make_float2(1.f, 0.f);
    float2 Uc = make_float2(0.f, 0.f);
    int base = c * CL;
    for (int i = 0; i < CL; i++) {
        float2 e = g_e[(base + i)*Pd + p];
        float2 u = g_u[(base + i)*Pd + p];
        Uc = cmul(e, Uc); Uc.x += u.x; Uc.y += u.y;
        E  = cmul(e, E);
    }
    g_Ec[c*Pd + p] = E;
    g_Uc[c*Pd + p] = Uc;
}

// ---------------- K4: scan over chunk composites (tiny, 1 warp) --------------
__global__ void k_scan(int nc) {
    int p = threadIdx.x;
    float2 s = make_float2(g_y0[2*p], g_y0[2*p+1]);
    for (int c = 0; c < nc; c++) {
        g_carry[c*Pd + p] = s;
        float2 E = g_Ec[c*Pd + p];
        float2 Uc = g_Uc[c*Pd + p];
        s = cmul(E, s); s.x += Uc.x; s.y += Uc.y;
    }
}

// ---------------- K5: replay with correct carries, write y_right -------------
__global__ void k_replay() {
    int c = blockIdx.x * (blockDim.x >> 5) + (threadIdx.x >> 5);
    int p = threadIdx.x & 31;
    float2 z = g_carry[c*Pd + p];
    int base = c * CL;
    float2* Y2 = (float2*)g_Y;
    for (int i = 0; i < CL; i++) {
        int n = base + i;
        float2 e = g_e[n*Pd + p];
        float2 u = g_u[n*Pd + p];
        z = cmul(e, z); z.x += u.x; z.y += u.y;
        Y2[n*Pd + p] = z;     // y_right[n][2p], y_right[n][2p+1]
    }
}

// ---------------- K6: outputs x_right = V y,  x_left = x_right - EA[:,mark] ---
__global__ void k_out(const float* __restrict__ Vmat,
                      const int*   __restrict__ marks,
                      float* __restrict__ out, int Nn) {
    __shared__ float Vs[Dd*65];
    __shared__ float Ys[4][Dd];
    int tid = threadIdx.x;
    for (int i = tid; i < Dd*Dd; i += 256) {
        int r = i >> 6, cc = i & 63;
        Vs[r*65 + cc] = Vmat[i];
    }
    int n0 = blockIdx.x * 64;
    int i  = tid & 63, rq = tid >> 6;
    for (int gblk = 0; gblk < 16; gblk++) {
        __syncthreads();
        int n = n0 + gblk*4 + rq;
        Ys[rq][i] = g_Y[n*Dd + i];
        __syncthreads();
        float acc = 0.f;
        #pragma unroll
        for (int k = 0; k < Dd; k++) acc = fmaf(Vs[i*65 + k], Ys[rq][k], acc);
        int mk = marks[n];
        out[n*Dd + i]            = acc;                       // x_right
        out[Nn*Dd + n*Dd + i]    = acc - g_EA[i*Kd + mk];     // x_left
    }
}

// ---------------- launch ------------------------------------------------------
extern "C" void kernel_launch(void* const* d_in, const int* in_sizes, int n_in,
                              void* d_out, int out_size) {
    const float* times = (const float*)d_in[0];
    const int*   marks = (const int*)  d_in[1];
    const float* u     = (const float*)d_in[2];
    const float* llr   = (const float*)d_in[3];
    const float* lim   = (const float*)d_in[4];
    const float* V     = (const float*)d_in[5];
    const float* B     = (const float*)d_in[6];
    const float* E     = (const float*)d_in[7];
    const float* alpha = (const float*)d_in[8];
    const float* gw    = (const float*)d_in[9];
    const float* gb    = (const float*)d_in[10];
    const float* x0    = (const float*)d_in[11];
    float* out = (float*)d_out;

    int Nn = in_sizes[0];          // 8192
    int nc = Nn / CL;              // 128 chunks

    k_inv<<<1, 256>>>(V);
    k_W  <<<(Dd*Hd + 255)/256, 256>>>(B);
    k_EA <<<(Dd*Kd + 255)/256, 256>>>(E, alpha);
    k_G  <<<(Dd*Kd + 255)/256, 256>>>(x0);
    k_features<<<Nn/64, 256>>>(times, marks, u, gw, gb, llr, lim);
    k_chunk <<<nc/4, 128>>>();
    k_scan  <<<1, 32>>>(nc);
    k_replay<<<nc/4, 128>>>();
    k_out   <<<Nn/64, 256>>>(V, marks, out, Nn);
}

// round 2
// speedup vs baseline: 1.0134x; 1.0134x over previous
#include <cuda_runtime.h>
#include <math.h>

#define NMAX 8192
#define Hd   512
#define Pd   32
#define Dd   64
#define Kd   100
#define CL   64          // chunk length == rows per k_features block
#define NCMAX (NMAX/CL)  // 128 chunks

// ---------------- scratch (static device globals; no allocation) -------------
__device__ float  g_Vinv[Dd*Dd];
__device__ float  g_W[Dd*Hd];        // V^-1 @ B
__device__ float  g_EA[Dd*Kd];       // E @ alpha
__device__ float  g_G[Dd*Kd];        // V^-1 @ E @ alpha
__device__ float  g_y0[Dd];          // V^-1 @ x0
__device__ float2 g_e[NMAX*Pd];      // per-step complex decay
__device__ float2 g_u[NMAX*Pd];      // per-step complex input
__device__ float2 g_Ec[NCMAX*Pd];    // chunk composite multiplier
__device__ float2 g_Uc[NCMAX*Pd];    // chunk composite offset
__device__ float2 g_carry[NCMAX*Pd]; // state entering each chunk

__device__ __forceinline__ float2 cmul(float2 a, float2 b) {
    return make_float2(a.x*b.x - a.y*b.y, a.x*b.y + a.y*b.x);
}
__device__ __forceinline__ float softplusf(float x) {
    return x > 0.f ? x + log1pf(expf(-x)) : log1pf(expf(x));
}

// ---------------- K1: 64x64 Gauss-Jordan inverse of V ------------------------
__global__ void k_inv(const float* __restrict__ V) {
    __shared__ float A[Dd][2*Dd + 1];
    __shared__ float f[Dd];
    int tid = threadIdx.x;
    for (int i = tid; i < Dd*Dd; i += blockDim.x) {
        int r = i >> 6, c = i & 63;
        A[r][c]      = V[i];
        A[r][Dd + c] = (r == c) ? 1.f : 0.f;
    }
    __syncthreads();
    for (int k = 0; k < Dd; k++) {
        float inv = 1.f / A[k][k];
        if (tid < 2*Dd) A[k][tid] *= inv;
        __syncthreads();
        if (tid < Dd) f[tid] = (tid == k) ? 0.f : A[tid][k];
        __syncthreads();
        for (int i = tid; i < Dd*2*Dd; i += blockDim.x) {
            int r = i >> 7, c = i & 127;
            if (r != k) A[r][c] -= f[r] * A[k][c];
        }
        __syncthreads();
    }
    for (int i = tid; i < Dd*Dd; i += blockDim.x) {
        int r = i >> 6, c = i & 63;
        g_Vinv[i] = A[r][Dd + c];
    }
}

// ---------------- K2: fused setup (block-specialized) -------------------------
// blocks 0..127 : W = Vinv @ B  (64x512, one element per thread)
// block  128    : EA = E@alpha (smem), then G = Vinv@EA, then y0 = Vinv@x0
__global__ void k_setup(const float* __restrict__ B,
                        const float* __restrict__ E,
                        const float* __restrict__ alpha,
                        const float* __restrict__ x0) {
    int b = blockIdx.x, tid = threadIdx.x;
    if (b < 128) {
        int idx = b * 256 + tid;              // 0..32767
        int d = idx >> 9, h = idx & 511;
        float acc = 0.f;
        #pragma unroll 16
        for (int k = 0; k < Dd; k++) acc = fmaf(g_Vinv[d*Dd + k], B[k*Hd + h], acc);
        g_W[idx] = acc;
    } else {
        __shared__ float sEA[Dd*Kd];          // 25.6 KB
        for (int i = tid; i < Dd*Kd; i += 256) {
            int d = i / Kd, kk = i % Kd;
            float acc = 0.f;
            #pragma unroll
            for (int r = 0; r < 32; r++) acc = fmaf(E[d*32 + r], alpha[r*Kd + kk], acc);
            sEA[i]  = acc;
            g_EA[i] = acc;
        }
        __syncthreads();
        for (int i = tid; i < Dd*Kd; i += 256) {
            int d = i / Kd, kk = i % Kd;
            float acc = 0.f;
            #pragma unroll 16
            for (int j = 0; j < Dd; j++) acc = fmaf(g_Vinv[d*Dd + j], sEA[j*Kd + kk], acc);
            g_G[i] = acc;
        }
        if (tid < Dd) {
            float acc = 0.f;
            #pragma unroll 16
            for (int k = 0; k < Dd; k++) acc = fmaf(g_Vinv[tid*Dd + k], x0[k], acc);
            g_y0[tid] = acc;
        }
    }
}

// ---------------- K3: per-step features + in-block chunk composite ------------
__global__ void k_features(const float* __restrict__ times,
                           const int*   __restrict__ marks,
                           const float* __restrict__ U,
                           const float* __restrict__ gw,
                           const float* __restrict__ gb,
                           const float* __restrict__ llr,
                           const float* __restrict__ lim) {
    __shared__ float sm[64*65 + 96*65];   // Us tile, Ws tile (padded)
    float* Us = sm;            // [64][65]
    float* Ws = sm + 64*65;    // [96][65]
    int tid = threadIdx.x;
    int n0  = blockIdx.x * 64;
    int tx = tid & 15, ty = tid >> 4;

    float acc[4][6];
    #pragma unroll
    for (int i = 0; i < 4; i++)
        #pragma unroll
        for (int j = 0; j < 6; j++) acc[i][j] = 0.f;

    for (int h0 = 0; h0 < Hd; h0 += 64) {
        __syncthreads();
        for (int i = tid; i < 64*16; i += 256) {
            int r = i >> 4, c4 = i & 15;
            float4 v = *(const float4*)&U[(n0 + r)*Hd + h0 + c4*4];
            float* dst = &Us[r*65 + c4*4];
            dst[0] = v.x; dst[1] = v.y; dst[2] = v.z; dst[3] = v.w;
        }
        for (int i = tid; i < 96*16; i += 256) {
            int r = i >> 4, c4 = i & 15;
            const float* src = (r < 32) ? &gw[r*Hd + h0 + c4*4]
                                        : &g_W[(r-32)*Hd + h0 + c4*4];
            float4 v = *(const float4*)src;
            float* dst = &Ws[r*65 + c4*4];
            dst[0] = v.x; dst[1] = v.y; dst[2] = v.z; dst[3] = v.w;
        }
        __syncthreads();
        #pragma unroll 4
        for (int h = 0; h < 64; h++) {
            float rv[4], cv[6];
            #pragma unroll
            for (int ri = 0; ri < 4; ri++) rv[ri] = Us[(ty + 16*ri)*65 + h];
            #pragma unroll
            for (int ci = 0; ci < 6; ci++) cv[ci] = Ws[(tx + 16*ci)*65 + h];
            #pragma unroll
            for (int ri = 0; ri < 4; ri++)
                #pragma unroll
                for (int ci = 0; ci < 6; ci++)
                    acc[ri][ci] = fmaf(rv[ri], cv[ci], acc[ri][ci]);
        }
    }

    __syncthreads();
    float* M = sm;  // 64 x 97
    #pragma unroll
    for (int ri = 0; ri < 4; ri++)
        #pragma unroll
        for (int ci = 0; ci < 6; ci++)
            M[(ty + 16*ri)*97 + (tx + 16*ci)] = acc[ri][ci];
    __syncthreads();

    for (int t = tid; t < 64*Pd; t += 256) {
        int r = t >> 5, p = t & 31;
        int n = n0 + r;
        float tn = times[n];
        float dt = tn - ((n > 0) ? times[n-1] : 0.f);
        float gate = softplusf(M[r*97 + p] + gb[p]);
        float re   = -softplusf(llr[p]) * gate;
        float im   = lim[p];
        float er = expf(re * dt);
        float th = im * dt;
        float a = er * cosf(th);
        float c = er * sinf(th);
        float denom = re*re + im*im;
        float nr = a - 1.f, ni = c;
        float qr = (nr*re + ni*im) / (denom + 1e-12f);
        float qi = (ni*re - nr*im) / (denom + 1e-12f);
        if (denom < 1e-8f) { qr = dt; qi = 0.f; }
        float wre = M[r*97 + 32 + 2*p];
        float wim = M[r*97 + 33 + 2*p];
        float pos = (dt > 0.f) ? 1.f : 0.f;
        int   mk  = marks[n];
        float ure = (qr*wre - qi*wim) * pos + g_G[(2*p)*Kd + mk];
        float uim = (qr*wim + qi*wre) * pos + g_G[(2*p+1)*Kd + mk];
        g_e[n*Pd + p] = make_float2(a, c);
        g_u[n*Pd + p] = make_float2(ure, uim);
    }

    // chunk composite: this block covers exactly chunk blockIdx.x
    __syncthreads();
    if (tid < 32) {
        int p = tid;
        float2 Ecomp = make_float2(1.f, 0.f);
        float2 Ucomp = make_float2(0.f, 0.f);
        #pragma unroll 8
        for (int i = 0; i < CL; i++) {
            float2 e = g_e[(n0 + i)*Pd + p];   // L1 hit: just written by this block
            float2 u = g_u[(n0 + i)*Pd + p];
            Ucomp = cmul(e, Ucomp); Ucomp.x += u.x; Ucomp.y += u.y;
            Ecomp = cmul(e, Ecomp);
        }
        g_Ec[blockIdx.x*Pd + p] = Ecomp;
        g_Uc[blockIdx.x*Pd + p] = Ucomp;
    }
}

// ---------------- K4: serial scan over chunk composites (tiny) ----------------
__global__ void k_scan(int nc) {
    int p = threadIdx.x;
    float2 s = make_float2(g_y0[2*p], g_y0[2*p+1]);
    #pragma unroll 4
    for (int c = 0; c < nc; c++) {
        g_carry[c*Pd + p] = s;
        float2 E = g_Ec[c*Pd + p];
        float2 Uc = g_Uc[c*Pd + p];
        s = cmul(E, s); s.x += Uc.x; s.y += Uc.y;
    }
}

// ---------------- K5: fused replay + output ----------------------------------
// One block per chunk. Warp 0 scans 64 steps into smem Ys; then all 256
// threads do the V matvec (float4 smem reads) and write both outputs.
__global__ void k_replay_out(const float* __restrict__ Vmat,
                             const int*   __restrict__ marks,
                             float* __restrict__ out, int Nn) {
    __shared__ float Vs[Dd*68];     // row-major V, stride 68 (float4-friendly)
    __shared__ float Ys[CL*68];     // y per row, stride 68
    __shared__ int   mks[CL];
    int tid = threadIdx.x;
    int cblk = blockIdx.x;
    int n0 = cblk * CL;

    for (int i = tid; i < Dd*Dd; i += 256) {
        int r = i >> 6, cc = i & 63;
        Vs[r*68 + cc] = Vmat[i];
    }
    if (tid < CL) mks[tid] = marks[n0 + tid];

    if (tid < 32) {
        int p = tid;
        float2 z = g_carry[cblk*Pd + p];
        #pragma unroll 8
        for (int i = 0; i < CL; i++) {
            float2 e = g_e[(n0 + i)*Pd + p];
            float2 u = g_u[(n0 + i)*Pd + p];
            z = cmul(e, z); z.x += u.x; z.y += u.y;
            Ys[i*68 + 2*p]     = z.x;
            Ys[i*68 + 2*p + 1] = z.y;
        }
    }
    __syncthreads();

    int i  = tid & 63;          // output dim
    int rq = tid >> 6;          // 4 rows in flight
    const float4* Vr = (const float4*)&Vs[i*68];
    #pragma unroll
    for (int g = 0; g < 16; g++) {
        int row = g*4 + rq;
        const float4* Yr = (const float4*)&Ys[row*68];
        float acc = 0.f;
        #pragma unroll
        for (int k4 = 0; k4 < 16; k4++) {
            float4 v = Vr[k4];
            float4 y = Yr[k4];
            acc = fmaf(v.x, y.x, acc);
            acc = fmaf(v.y, y.y, acc);
            acc = fmaf(v.z, y.z, acc);
            acc = fmaf(v.w, y.w, acc);
        }
        int n  = n0 + row;
        int mk = mks[row];
        out[n*Dd + i]         = acc;                    // x_right
        out[Nn*Dd + n*Dd + i] = acc - g_EA[i*Kd + mk];  // x_left
    }
}

// ---------------- launch ------------------------------------------------------
extern "C" void kernel_launch(void* const* d_in, const int* in_sizes, int n_in,
                              void* d_out, int out_size) {
    const float* times = (const float*)d_in[0];
    const int*   marks = (const int*)  d_in[1];
    const float* u     = (const float*)d_in[2];
    const float* llr   = (const float*)d_in[3];
    const float* lim   = (const float*)d_in[4];
    const float* V     = (const float*)d_in[5];
    const float* B     = (const float*)d_in[6];
    const float* E     = (const float*)d_in[7];
    const float* alpha = (const float*)d_in[8];
    const float* gw    = (const float*)d_in[9];
    const float* gb    = (const float*)d_in[10];
    const float* x0    = (const float*)d_in[11];
    float* out = (float*)d_out;

    int Nn = in_sizes[0];          // 8192
    int nc = Nn / CL;              // 128 chunks

    k_inv<<<1, 256>>>(V);
    k_setup<<<129, 256>>>(B, E, alpha, x0);
    k_features<<<Nn/64, 256>>>(times, marks, u, gw, gb, llr, lim);
    k_scan<<<1, 32>>>(nc);
    k_replay_out<<<nc, 256>>>(V, marks, out, Nn);
}

// round 3
// speedup vs baseline: 1.1307x; 1.1158x over previous
#include <cuda_runtime.h>
#include <math.h>

#define NMAX 8192
#define Hd   512
#define Pd   32
#define Dd   64
#define Kd   100
#define CL   64          // chunk length == rows per k_features block
#define NCMAX (NMAX/CL)  // 128 chunks

// ---------------- scratch (static device globals; no allocation) -------------
__device__ float  g_Vinv[Dd*Dd];
__device__ float  g_W[Dd*Hd];        // V^-1 @ B
__device__ float  g_EA[Dd*Kd];       // E @ alpha
__device__ float  g_G[Dd*Kd];        // V^-1 @ E @ alpha
__device__ float  g_y0[Dd];          // V^-1 @ x0
__device__ float2 g_e[NMAX*Pd];      // per-step complex decay
__device__ float2 g_u[NMAX*Pd];      // per-step complex input
__device__ float2 g_Ec[NCMAX*Pd];    // chunk composite multiplier
__device__ float2 g_Uc[NCMAX*Pd];    // chunk composite offset
__device__ float2 g_carry[NCMAX*Pd]; // state entering each chunk

__device__ __forceinline__ float2 cmul(float2 a, float2 b) {
    return make_float2(a.x*b.x - a.y*b.y, a.x*b.y + a.y*b.x);
}
__device__ __forceinline__ float softplusf(float x) {
    return x > 0.f ? x + log1pf(expf(-x)) : log1pf(expf(x));
}

// ---------------- K1: 64x64 Gauss-Jordan inverse of V ------------------------
__global__ void k_inv(const float* __restrict__ V) {
    __shared__ float A[Dd][2*Dd + 1];
    __shared__ float f[Dd];
    int tid = threadIdx.x;
    for (int i = tid; i < Dd*Dd; i += blockDim.x) {
        int r = i >> 6, c = i & 63;
        A[r][c]      = V[i];
        A[r][Dd + c] = (r == c) ? 1.f : 0.f;
    }
    __syncthreads();
    for (int k = 0; k < Dd; k++) {
        float inv = 1.f / A[k][k];
        if (tid < 2*Dd) A[k][tid] *= inv;
        __syncthreads();
        if (tid < Dd) f[tid] = (tid == k) ? 0.f : A[tid][k];
        __syncthreads();
        for (int i = tid; i < Dd*2*Dd; i += blockDim.x) {
            int r = i >> 7, c = i & 127;
            if (r != k) A[r][c] -= f[r] * A[k][c];
        }
        __syncthreads();
    }
    for (int i = tid; i < Dd*Dd; i += blockDim.x) {
        int r = i >> 6, c = i & 63;
        g_Vinv[i] = A[r][Dd + c];
    }
}

// ---------------- K2: fused setup (block-specialized) -------------------------
__global__ void k_setup(const float* __restrict__ B,
                        const float* __restrict__ E,
                        const float* __restrict__ alpha,
                        const float* __restrict__ x0) {
    int b = blockIdx.x, tid = threadIdx.x;
    if (b < 128) {
        int idx = b * 256 + tid;              // 0..32767
        int d = idx >> 9, h = idx & 511;
        float acc = 0.f;
        #pragma unroll 16
        for (int k = 0; k < Dd; k++) acc = fmaf(g_Vinv[d*Dd + k], B[k*Hd + h], acc);
        g_W[idx] = acc;
    } else {
        __shared__ float sEA[Dd*Kd];
        for (int i = tid; i < Dd*Kd; i += 256) {
            int d = i / Kd, kk = i % Kd;
            float acc = 0.f;
            #pragma unroll
            for (int r = 0; r < 32; r++) acc = fmaf(E[d*32 + r], alpha[r*Kd + kk], acc);
            sEA[i]  = acc;
            g_EA[i] = acc;
        }
        __syncthreads();
        for (int i = tid; i < Dd*Kd; i += 256) {
            int d = i / Kd, kk = i % Kd;
            float acc = 0.f;
            #pragma unroll 16
            for (int j = 0; j < Dd; j++) acc = fmaf(g_Vinv[d*Dd + j], sEA[j*Kd + kk], acc);
            g_G[i] = acc;
        }
        if (tid < Dd) {
            float acc = 0.f;
            #pragma unroll 16
            for (int k = 0; k < Dd; k++) acc = fmaf(g_Vinv[tid*Dd + k], x0[k], acc);
            g_y0[tid] = acc;
        }
    }
}

// ---------------- K3: per-step features + in-block chunk composite ------------
// Thread mapping fixed for bank conflicts: row = ri*16+ty, col = ci*16+tx
// -> column smem reads have lane stride 65 floats (bank = tx), conflict-free.
__global__ void k_features(const float* __restrict__ times,
                           const int*   __restrict__ marks,
                           const float* __restrict__ U,
                           const float* __restrict__ gw,
                           const float* __restrict__ gb,
                           const float* __restrict__ llr,
                           const float* __restrict__ lim) {
    __shared__ float sm[64*65 + 96*65];
    float* Us = sm;            // [64][65]
    float* Ws = sm + 64*65;    // [96][65]
    int tid = threadIdx.x;
    int n0  = blockIdx.x * 64;
    int tx = tid & 15, ty = tid >> 4;

    float acc[4][6];
    #pragma unroll
    for (int i = 0; i < 4; i++)
        #pragma unroll
        for (int j = 0; j < 6; j++) acc[i][j] = 0.f;

    for (int h0 = 0; h0 < Hd; h0 += 64) {
        __syncthreads();
        for (int i = tid; i < 64*16; i += 256) {
            int r = i >> 4, c4 = i & 15;
            float4 v = *(const float4*)&U[(n0 + r)*Hd + h0 + c4*4];
            float* dst = &Us[r*65 + c4*4];
            dst[0] = v.x; dst[1] = v.y; dst[2] = v.z; dst[3] = v.w;
        }
        for (int i = tid; i < 96*16; i += 256) {
            int r = i >> 4, c4 = i & 15;
            const float* src = (r < 32) ? &gw[r*Hd + h0 + c4*4]
                                        : &g_W[(r-32)*Hd + h0 + c4*4];
            float4 v = *(const float4*)src;
            float* dst = &Ws[r*65 + c4*4];
            dst[0] = v.x; dst[1] = v.y; dst[2] = v.z; dst[3] = v.w;
        }
        __syncthreads();
        #pragma unroll 4
        for (int h = 0; h < 64; h++) {
            float rv[4], cv[6];
            #pragma unroll
            for (int ri = 0; ri < 4; ri++) rv[ri] = Us[(ri*16 + ty)*65 + h];
            #pragma unroll
            for (int ci = 0; ci < 6; ci++) cv[ci] = Ws[(ci*16 + tx)*65 + h];
            #pragma unroll
            for (int ri = 0; ri < 4; ri++)
                #pragma unroll
                for (int ci = 0; ci < 6; ci++)
                    acc[ri][ci] = fmaf(rv[ri], cv[ci], acc[ri][ci]);
        }
    }

    __syncthreads();
    float* M = sm;  // 64 x 97
    #pragma unroll
    for (int ri = 0; ri < 4; ri++)
        #pragma unroll
        for (int ci = 0; ci < 6; ci++)
            M[(ri*16 + ty)*97 + (ci*16 + tx)] = acc[ri][ci];
    __syncthreads();

    for (int t = tid; t < 64*Pd; t += 256) {
        int r = t >> 5, p = t & 31;
        int n = n0 + r;
        float tn = times[n];
        float dt = tn - ((n > 0) ? times[n-1] : 0.f);
        float gate = softplusf(M[r*97 + p] + gb[p]);
        float re   = -softplusf(llr[p]) * gate;
        float im   = lim[p];
        float er = expf(re * dt);
        float th = im * dt;
        float a = er * cosf(th);
        float c = er * sinf(th);
        float denom = re*re + im*im;
        float nr = a - 1.f, ni = c;
        float qr = (nr*re + ni*im) / (denom + 1e-12f);
        float qi = (ni*re - nr*im) / (denom + 1e-12f);
        if (denom < 1e-8f) { qr = dt; qi = 0.f; }
        float wre = M[r*97 + 32 + 2*p];
        float wim = M[r*97 + 33 + 2*p];
        float pos = (dt > 0.f) ? 1.f : 0.f;
        int   mk  = marks[n];
        float ure = (qr*wre - qi*wim) * pos + g_G[(2*p)*Kd + mk];
        float uim = (qr*wim + qi*wre) * pos + g_G[(2*p+1)*Kd + mk];
        g_e[n*Pd + p] = make_float2(a, c);
        g_u[n*Pd + p] = make_float2(ure, uim);
    }

    __syncthreads();
    if (tid < 32) {
        int p = tid;
        float2 Ecomp = make_float2(1.f, 0.f);
        float2 Ucomp = make_float2(0.f, 0.f);
        #pragma unroll 16
        for (int i = 0; i < CL; i++) {
            float2 e = g_e[(n0 + i)*Pd + p];
            float2 u = g_u[(n0 + i)*Pd + p];
            Ucomp = cmul(e, Ucomp); Ucomp.x += u.x; Ucomp.y += u.y;
            Ecomp = cmul(e, Ecomp);
        }
        g_Ec[blockIdx.x*Pd + p] = Ecomp;
        g_Uc[blockIdx.x*Pd + p] = Ucomp;
    }
}

// ---------------- K4: parallel scan over chunk composites ---------------------
// One block, 32 warps. Warp w = mode p. Kogge-Stone warp scan per 32-chunk
// segment; segments chained through a register carry.
__global__ void k_scan(int nc) {
    int w    = threadIdx.x >> 5;   // p
    int lane = threadIdx.x & 31;
    float2 carryS = make_float2(g_y0[2*w], g_y0[2*w+1]);
    int nseg = nc >> 5;
    for (int seg = 0; seg < nseg; seg++) {
        int c = (seg << 5) + lane;
        float2 E = g_Ec[c*Pd + w];
        float2 U = g_Uc[c*Pd + w];
        #pragma unroll
        for (int off = 1; off < 32; off <<= 1) {
            float Ex = __shfl_up_sync(0xFFFFFFFFu, E.x, off);
            float Ey = __shfl_up_sync(0xFFFFFFFFu, E.y, off);
            float Ux = __shfl_up_sync(0xFFFFFFFFu, U.x, off);
            float Uy = __shfl_up_sync(0xFFFFFFFFu, U.y, off);
            if (lane >= off) {
                float2 Ep = make_float2(Ex, Ey);
                float2 t  = cmul(E, make_float2(Ux, Uy));
                U.x += t.x; U.y += t.y;
                E = cmul(E, Ep);
            }
        }
        float2 s_after = cmul(E, carryS);
        s_after.x += U.x; s_after.y += U.y;
        float px = __shfl_up_sync(0xFFFFFFFFu, s_after.x, 1);
        float py = __shfl_up_sync(0xFFFFFFFFu, s_after.y, 1);
        float2 carry_c = (lane == 0) ? carryS : make_float2(px, py);
        g_carry[c*Pd + w] = carry_c;
        carryS.x = __shfl_sync(0xFFFFFFFFu, s_after.x, 31);
        carryS.y = __shfl_sync(0xFFFFFFFFu, s_after.y, 31);
    }
}

// ---------------- K5: fused replay + output ----------------------------------
__global__ void k_replay_out(const float* __restrict__ Vmat,
                             const int*   __restrict__ marks,
                             float* __restrict__ out, int Nn) {
    __shared__ float Vs[Dd*68];
    __shared__ float Ys[CL*68];
    __shared__ int   mks[CL];
    int tid = threadIdx.x;
    int cblk = blockIdx.x;
    int n0 = cblk * CL;

    for (int i = tid; i < Dd*Dd; i += 256) {
        int r = i >> 6, cc = i & 63;
        Vs[r*68 + cc] = Vmat[i];
    }
    if (tid < CL) mks[tid] = marks[n0 + tid];

    if (tid < 32) {
        int p = tid;
        float2 z = g_carry[cblk*Pd + p];
        #pragma unroll 16
        for (int i = 0; i < CL; i++) {
            float2 e = g_e[(n0 + i)*Pd + p];
            float2 u = g_u[(n0 + i)*Pd + p];
            z = cmul(e, z); z.x += u.x; z.y += u.y;
            Ys[i*68 + 2*p]     = z.x;
            Ys[i*68 + 2*p + 1] = z.y;
        }
    }
    __syncthreads();

    int i  = tid & 63;          // output dim
    int rq = tid >> 6;          // 4 rows in flight
    const float4* Vr = (const float4*)&Vs[i*68];
    #pragma unroll
    for (int g = 0; g < 16; g++) {
        int row = g*4 + rq;
        const float4* Yr = (const float4*)&Ys[row*68];
        float acc = 0.f;
        #pragma unroll
        for (int k4 = 0; k4 < 16; k4++) {
            float4 v = Vr[k4];
            float4 y = Yr[k4];
            acc = fmaf(v.x, y.x, acc);
            acc = fmaf(v.y, y.y, acc);
            acc = fmaf(v.z, y.z, acc);
            acc = fmaf(v.w, y.w, acc);
        }
        int n  = n0 + row;
        int mk = mks[row];
        out[n*Dd + i]         = acc;                    // x_right
        out[Nn*Dd + n*Dd + i] = acc - g_EA[i*Kd + mk];  // x_left
    }
}

// ---------------- launch ------------------------------------------------------
extern "C" void kernel_launch(void* const* d_in, const int* in_sizes, int n_in,
                              void* d_out, int out_size) {
    const float* times = (const float*)d_in[0];
    const int*   marks = (const int*)  d_in[1];
    const float* u     = (const float*)d_in[2];
    const float* llr   = (const float*)d_in[3];
    const float* lim   = (const float*)d_in[4];
    const float* V     = (const float*)d_in[5];
    const float* B     = (const float*)d_in[6];
    const float* E     = (const float*)d_in[7];
    const float* alpha = (const float*)d_in[8];
    const float* gw    = (const float*)d_in[9];
    const float* gb    = (const float*)d_in[10];
    const float* x0    = (const float*)d_in[11];
    float* out = (float*)d_out;

    int Nn = in_sizes[0];          // 8192
    int nc = Nn / CL;              // 128 chunks

    k_inv<<<1, 256>>>(V);
    k_setup<<<129, 256>>>(B, E, alpha, x0);
    k_features<<<Nn/64, 256>>>(times, marks, u, gw, gb, llr, lim);
    k_scan<<<1, 1024>>>(nc);
    k_replay_out<<<nc, 256>>>(V, marks, out, Nn);
}

// round 4
// speedup vs baseline: 1.1311x; 1.0004x over previous
#include <cuda_runtime.h>
#include <math.h>

#define NMAX 8192
#define Hd   512
#define Pd   32
#define Dd   64
#define Kd   100
#define CL   8            // chunk length for the parallel scan
#define NCMAX (NMAX/CL)   // 1024 chunks

// ---------------- scratch (static device globals; no allocation) -------------
__device__ float  g_Vinv[Dd*Dd];
__device__ float  g_W[Dd*Hd];        // V^-1 @ B
__device__ float  g_EA[Dd*Kd];       // E @ alpha
__device__ float  g_G[Dd*Kd];        // V^-1 @ E @ alpha
__device__ float  g_y0[Dd];          // V^-1 @ x0
__device__ float2 g_e[NMAX*Pd];      // per-step complex decay   [n][p]
__device__ float2 g_u[NMAX*Pd];      // per-step complex input   [n][p]
__device__ float2 g_Ec[NCMAX*Pd];    // chunk composite multiplier [p][c] (transposed)
__device__ float2 g_Uc[NCMAX*Pd];    // chunk composite offset     [p][c]
__device__ float2 g_carry[NCMAX*Pd]; // state entering each chunk  [c][p]

__device__ __forceinline__ float2 cmul(float2 a, float2 b) {
    return make_float2(a.x*b.x - a.y*b.y, a.x*b.y + a.y*b.x);
}
__device__ __forceinline__ float softplus_fast(float x) {
    return x > 0.f ? x + log1pf(__expf(-x)) : log1pf(__expf(x));
}

// ---------------- K1: 64x64 Gauss-Jordan inverse of V ------------------------
__global__ void k_inv(const float* __restrict__ V) {
    __shared__ float A[Dd][2*Dd + 1];
    __shared__ float f[Dd];
    int tid = threadIdx.x;
    for (int i = tid; i < Dd*Dd; i += blockDim.x) {
        int r = i >> 6, c = i & 63;
        A[r][c]      = V[i];
        A[r][Dd + c] = (r == c) ? 1.f : 0.f;
    }
    __syncthreads();
    for (int k = 0; k < Dd; k++) {
        float inv = 1.f / A[k][k];
        if (tid < 2*Dd) A[k][tid] *= inv;
        __syncthreads();
        if (tid < Dd) f[tid] = (tid == k) ? 0.f : A[tid][k];
        __syncthreads();
        for (int i = tid; i < Dd*2*Dd; i += blockDim.x) {
            int r = i >> 7, c = i & 127;
            if (r != k) A[r][c] -= f[r] * A[k][c];
        }
        __syncthreads();
    }
    for (int i = tid; i < Dd*Dd; i += blockDim.x) {
        int r = i >> 6, c = i & 63;
        g_Vinv[i] = A[r][Dd + c];
    }
}

// ---------------- K2: fused setup (block-specialized) -------------------------
__global__ void k_setup(const float* __restrict__ B,
                        const float* __restrict__ E,
                        const float* __restrict__ alpha,
                        const float* __restrict__ x0) {
    int b = blockIdx.x, tid = threadIdx.x;
    if (b < 128) {
        int idx = b * 256 + tid;              // 0..32767
        int d = idx >> 9, h = idx & 511;
        float acc = 0.f;
        #pragma unroll 16
        for (int k = 0; k < Dd; k++) acc = fmaf(g_Vinv[d*Dd + k], B[k*Hd + h], acc);
        g_W[idx] = acc;
    } else {
        __shared__ float sEA[Dd*Kd];
        for (int i = tid; i < Dd*Kd; i += 256) {
            int d = i / Kd, kk = i % Kd;
            float acc = 0.f;
            #pragma unroll
            for (int r = 0; r < 32; r++) acc = fmaf(E[d*32 + r], alpha[r*Kd + kk], acc);
            sEA[i]  = acc;
            g_EA[i] = acc;
        }
        __syncthreads();
        for (int i = tid; i < Dd*Kd; i += 256) {
            int d = i / Kd, kk = i % Kd;
            float acc = 0.f;
            #pragma unroll 16
            for (int j = 0; j < Dd; j++) acc = fmaf(g_Vinv[d*Dd + j], sEA[j*Kd + kk], acc);
            g_G[i] = acc;
        }
        if (tid < Dd) {
            float acc = 0.f;
            #pragma unroll 16
            for (int k = 0; k < Dd; k++) acc = fmaf(g_Vinv[tid*Dd + k], x0[k], acc);
            g_y0[tid] = acc;
        }
    }
}

// ---------------- K3: features GEMM + transcendentals + chunk composites ------
// 512 threads. Tile 64 rows x 96 cols over H=512.
// tx = tid&31 -> cols {tx, tx+32, tx+64} (lane stride 65 in smem: conflict-free)
// ty = tid>>5 -> rows {4ty..4ty+3}      (uniform in warp: broadcast)
__global__ void __launch_bounds__(512, 1)
k_features(const float* __restrict__ times,
           const int*   __restrict__ marks,
           const float* __restrict__ U,
           const float* __restrict__ gw,
           const float* __restrict__ gb,
           const float* __restrict__ llr,
           const float* __restrict__ lim,
           int nc) {
    __shared__ float sm[160*65];
    float* Us = sm;            // [64][65]
    float* Ws = sm + 64*65;    // [96][65]
    int tid = threadIdx.x;
    int n0  = blockIdx.x * 64;
    int tx = tid & 31, ty = tid >> 5;

    float acc[4][3];
    #pragma unroll
    for (int i = 0; i < 4; i++)
        #pragma unroll
        for (int j = 0; j < 3; j++) acc[i][j] = 0.f;

    for (int h0 = 0; h0 < Hd; h0 += 64) {
        __syncthreads();
        #pragma unroll
        for (int i = tid; i < 64*16; i += 512) {
            int r = i >> 4, c4 = i & 15;
            float4 v = *(const float4*)&U[(n0 + r)*Hd + h0 + c4*4];
            float* dst = &Us[r*65 + c4*4];
            dst[0] = v.x; dst[1] = v.y; dst[2] = v.z; dst[3] = v.w;
        }
        #pragma unroll
        for (int i = tid; i < 96*16; i += 512) {
            int r = i >> 4, c4 = i & 15;
            const float* src = (r < 32) ? &gw[r*Hd + h0 + c4*4]
                                        : &g_W[(r-32)*Hd + h0 + c4*4];
            float4 v = *(const float4*)src;
            float* dst = &Ws[r*65 + c4*4];
            dst[0] = v.x; dst[1] = v.y; dst[2] = v.z; dst[3] = v.w;
        }
        __syncthreads();
        #pragma unroll 8
        for (int h = 0; h < 64; h++) {
            float rv[4], cv[3];
            #pragma unroll
            for (int ri = 0; ri < 4; ri++) rv[ri] = Us[(ty*4 + ri)*65 + h];
            #pragma unroll
            for (int ci = 0; ci < 3; ci++) cv[ci] = Ws[(tx + 32*ci)*65 + h];
            #pragma unroll
            for (int ri = 0; ri < 4; ri++)
                #pragma unroll
                for (int ci = 0; ci < 3; ci++)
                    acc[ri][ci] = fmaf(rv[ri], cv[ci], acc[ri][ci]);
        }
    }

    __syncthreads();
    float* M = sm;  // 64 x 97 (cols 0..31 gate_pre, 32..95 w)
    #pragma unroll
    for (int ri = 0; ri < 4; ri++)
        #pragma unroll
        for (int ci = 0; ci < 3; ci++)
            M[(ty*4 + ri)*97 + (tx + 32*ci)] = acc[ri][ci];
    __syncthreads();

    #pragma unroll
    for (int t = tid; t < 64*Pd; t += 512) {
        int r = t >> 5, p = t & 31;
        int n = n0 + r;
        float tn = times[n];
        float dt = tn - ((n > 0) ? times[n-1] : 0.f);
        float gate = softplus_fast(M[r*97 + p] + gb[p]);
        float re   = -softplus_fast(llr[p]) * gate;
        float im   = lim[p];
        float er = __expf(re * dt);
        float th = im * dt;
        float a = er * __cosf(th);
        float c = er * __sinf(th);
        float denom = re*re + im*im;
        float nr = a - 1.f, ni = c;
        float inv_d = __fdividef(1.f, denom + 1e-12f);
        float qr = (nr*re + ni*im) * inv_d;
        float qi = (ni*re - nr*im) * inv_d;
        if (denom < 1e-8f) { qr = dt; qi = 0.f; }
        float wre = M[r*97 + 32 + 2*p];
        float wim = M[r*97 + 33 + 2*p];
        float pos = (dt > 0.f) ? 1.f : 0.f;
        int   mk  = marks[n];
        float ure = (qr*wre - qi*wim) * pos + g_G[(2*p)*Kd + mk];
        float uim = (qr*wim + qi*wre) * pos + g_G[(2*p+1)*Kd + mk];
        g_e[n*Pd + p] = make_float2(a, c);
        g_u[n*Pd + p] = make_float2(ure, uim);
    }

    // chunk composites: 8 chunks of 8 steps; warps 0..7, one chunk each
    __syncthreads();
    int w = tid >> 5, lane = tid & 31;
    if (w < 8) {
        int cglob = blockIdx.x * 8 + w;
        int base  = n0 + w * 8;
        float2 Ecomp = make_float2(1.f, 0.f);
        float2 Ucomp = make_float2(0.f, 0.f);
        #pragma unroll
        for (int i = 0; i < CL; i++) {
            float2 e = g_e[(base + i)*Pd + lane];   // L1 hit
            float2 u = g_u[(base + i)*Pd + lane];
            Ucomp = cmul(e, Ucomp); Ucomp.x += u.x; Ucomp.y += u.y;
            Ecomp = cmul(e, Ecomp);
        }
        g_Ec[lane*nc + cglob] = Ecomp;   // transposed: [p][c]
        g_Uc[lane*nc + cglob] = Ucomp;
    }
}

// ---------------- K4: parallel scan over chunk composites ---------------------
// One block, 32 warps. Warp w = mode p. Kogge-Stone warp scan per 32-chunk
// segment (coalesced loads via transposed layout); carry chained across segs.
__global__ void k_scan(int nc) {
    int w    = threadIdx.x >> 5;   // p
    int lane = threadIdx.x & 31;
    float2 carryS = make_float2(g_y0[2*w], g_y0[2*w+1]);
    int nseg = nc >> 5;
    for (int seg = 0; seg < nseg; seg++) {
        int c = (seg << 5) + lane;
        float2 E = g_Ec[w*nc + c];
        float2 U = g_Uc[w*nc + c];
        #pragma unroll
        for (int off = 1; off < 32; off <<= 1) {
            float Ex = __shfl_up_sync(0xFFFFFFFFu, E.x, off);
            float Ey = __shfl_up_sync(0xFFFFFFFFu, E.y, off);
            float Ux = __shfl_up_sync(0xFFFFFFFFu, U.x, off);
            float Uy = __shfl_up_sync(0xFFFFFFFFu, U.y, off);
            if (lane >= off) {
                float2 Ep = make_float2(Ex, Ey);
                float2 t  = cmul(E, make_float2(Ux, Uy));
                U.x += t.x; U.y += t.y;
                E = cmul(E, Ep);
            }
        }
        float2 s_after = cmul(E, carryS);
        s_after.x += U.x; s_after.y += U.y;
        float px = __shfl_up_sync(0xFFFFFFFFu, s_after.x, 1);
        float py = __shfl_up_sync(0xFFFFFFFFu, s_after.y, 1);
        float2 carry_c = (lane == 0) ? carryS : make_float2(px, py);
        g_carry[c*Pd + w] = carry_c;
        carryS.x = __shfl_sync(0xFFFFFFFFu, s_after.x, 31);
        carryS.y = __shfl_sync(0xFFFFFFFFu, s_after.y, 31);
    }
}

// ---------------- K5: fused replay + output ----------------------------------
// 256 threads / block, 64 rows. Warps 0..7 each replay one 8-step chunk in
// parallel; then all threads do the V matvec and write both outputs.
__global__ void k_replay_out(const float* __restrict__ Vmat,
                             const int*   __restrict__ marks,
                             float* __restrict__ out, int Nn) {
    __shared__ float Vs[Dd*68];
    __shared__ float Ys[64*68];
    __shared__ int   mks[64];
    int tid = threadIdx.x;
    int n0 = blockIdx.x * 64;

    for (int i = tid; i < Dd*Dd; i += 256) {
        int r = i >> 6, cc = i & 63;
        Vs[r*68 + cc] = Vmat[i];
    }
    if (tid < 64) mks[tid] = marks[n0 + tid];

    int w = tid >> 5, lane = tid & 31;
    {
        int chunk = blockIdx.x * 8 + w;
        int base  = n0 + w * 8;
        float2 z = g_carry[chunk*Pd + lane];
        #pragma unroll
        for (int i = 0; i < CL; i++) {
            float2 e = g_e[(base + i)*Pd + lane];
            float2 u = g_u[(base + i)*Pd + lane];
            z = cmul(e, z); z.x += u.x; z.y += u.y;
            Ys[(w*8 + i)*68 + 2*lane]     = z.x;
            Ys[(w*8 + i)*68 + 2*lane + 1] = z.y;
        }
    }
    __syncthreads();

    int i  = tid & 63;          // output dim
    int rq = tid >> 6;          // 4 rows in flight
    const float4* Vr = (const float4*)&Vs[i*68];
    #pragma unroll
    for (int g = 0; g < 16; g++) {
        int row = g*4 + rq;
        const float4* Yr = (const float4*)&Ys[row*68];
        float acc = 0.f;
        #pragma unroll
        for (int k4 = 0; k4 < 16; k4++) {
            float4 v = Vr[k4];
            float4 y = Yr[k4];
            acc = fmaf(v.x, y.x, acc);
            acc = fmaf(v.y, y.y, acc);
            acc = fmaf(v.z, y.z, acc);
            acc = fmaf(v.w, y.w, acc);
        }
        int n  = n0 + row;
        int mk = mks[row];
        out[n*Dd + i]         = acc;                    // x_right
        out[Nn*Dd + n*Dd + i] = acc - g_EA[i*Kd + mk];  // x_left
    }
}

// ---------------- launch ------------------------------------------------------
extern "C" void kernel_launch(void* const* d_in, const int* in_sizes, int n_in,
                              void* d_out, int out_size) {
    const float* times = (const float*)d_in[0];
    const int*   marks = (const int*)  d_in[1];
    const float* u     = (const float*)d_in[2];
    const float* llr   = (const float*)d_in[3];
    const float* lim   = (const float*)d_in[4];
    const float* V     = (const float*)d_in[5];
    const float* B     = (const float*)d_in[6];
    const float* E     = (const float*)d_in[7];
    const float* alpha = (const float*)d_in[8];
    const float* gw    = (const float*)d_in[9];
    const float* gb    = (const float*)d_in[10];
    const float* x0    = (const float*)d_in[11];
    float* out = (float*)d_out;

    int Nn = in_sizes[0];          // 8192
    int nc = Nn / CL;              // 1024 chunks

    k_inv<<<1, 256>>>(V);
    k_setup<<<129, 256>>>(B, E, alpha, x0);
    k_features<<<Nn/64, 512>>>(times, marks, u, gw, gb, llr, lim, nc);
    k_scan<<<1, 1024>>>(nc);
    k_replay_out<<<Nn/64, 256>>>(V, marks, out, Nn);
}

// round 6
// speedup vs baseline: 1.3369x; 1.1819x over previous
#include <cuda_runtime.h>
#include <math.h>

#define NMAX 8192
#define Hd   512
#define Pd   32
#define Dd   64
#define Kd   100
#define CL   8            // chunk length for the parallel scan
#define NCMAX (NMAX/CL)   // 1024 chunks

// ---------------- scratch (static device globals; no allocation) -------------
__device__ float  g_Vinv[Dd*Dd];
__device__ float  g_W[Dd*Hd];        // V^-1 @ B
__device__ float  g_EA[Dd*Kd];       // E @ alpha
__device__ float  g_G[Dd*Kd];        // V^-1 @ E @ alpha
__device__ float  g_y0[Dd];          // V^-1 @ x0
__device__ float2 g_e[NMAX*Pd];      // per-step complex decay   [n][p]
__device__ float2 g_u[NMAX*Pd];      // per-step complex input   [n][p]
__device__ float2 g_Ec[NCMAX*Pd];    // chunk composite multiplier [p][c]
__device__ float2 g_Uc[NCMAX*Pd];    // chunk composite offset     [p][c]
__device__ float2 g_carry[NCMAX*Pd]; // state entering each chunk  [c][p]

__device__ __forceinline__ float2 cmul(float2 a, float2 b) {
    return make_float2(a.x*b.x - a.y*b.y, a.x*b.y + a.y*b.x);
}
__device__ __forceinline__ float softplus_fast(float x) {
    return x > 0.f ? x + log1pf(__expf(-x)) : log1pf(__expf(x));
}

// ---------------- K1: 64x64 inverse, elimination w/o pivot normalization -----
__global__ void __launch_bounds__(512, 1) k_inv(const float* __restrict__ V) {
    __shared__ float A[Dd][129];
    __shared__ float f[Dd];
    int tid = threadIdx.x;
    for (int i = tid; i < Dd*Dd; i += 512) {
        int r = i >> 6, c = i & 63;
        A[r][c]      = V[i];
        A[r][Dd + c] = (r == c) ? 1.f : 0.f;
    }
    __syncthreads();
    int r  = tid >> 3;
    int c0 = (tid & 7) * 16;
    for (int k = 0; k < Dd; k++) {
        if (tid < Dd) {
            float invp = 1.f / A[k][k];
            f[tid] = (tid == k) ? 0.f : A[tid][k] * invp;
        }
        __syncthreads();
        float fr = f[r];
        if (r != k) {
            #pragma unroll
            for (int j = 0; j < 16; j++)
                A[r][c0 + j] = fmaf(-fr, A[k][c0 + j], A[r][c0 + j]);
        }
        __syncthreads();
    }
    for (int i = tid; i < Dd*Dd; i += 512) {
        int rr = i >> 6, cc = i & 63;
        g_Vinv[i] = A[rr][Dd + cc] / A[rr][rr];
    }
}

// ---------------- K2a: EA = E@alpha, G = Vinv@EA, y0 = Vinv@x0 (1 block) -----
__global__ void k_setupEA(const float* __restrict__ E,
                          const float* __restrict__ alpha,
                          const float* __restrict__ x0) {
    __shared__ float sEA[Dd*Kd];
    int tid = threadIdx.x;
    for (int i = tid; i < Dd*Kd; i += 256) {
        int d = i / Kd, kk = i % Kd;
        float acc = 0.f;
        #pragma unroll
        for (int r = 0; r < 32; r++) acc = fmaf(E[d*32 + r], alpha[r*Kd + kk], acc);
        sEA[i]  = acc;
        g_EA[i] = acc;
    }
    __syncthreads();
    for (int i = tid; i < Dd*Kd; i += 256) {
        int d = i / Kd, kk = i % Kd;
        float acc = 0.f;
        #pragma unroll 16
        for (int j = 0; j < Dd; j++) acc = fmaf(g_Vinv[d*Dd + j], sEA[j*Kd + kk], acc);
        g_G[i] = acc;
    }
    if (tid < Dd) {
        float acc = 0.f;
        #pragma unroll 16
        for (int k = 0; k < Dd; k++) acc = fmaf(g_Vinv[tid*Dd + k], x0[k], acc);
        g_y0[tid] = acc;
    }
}

// ---------------- K2b: W = Vinv @ B  (64x512) --------------------------------
__global__ void k_setupW(const float* __restrict__ B) {
    int idx = blockIdx.x * 512 + threadIdx.x;
    int d = idx >> 9, h = idx & 511;
    float acc = 0.f;
    #pragma unroll 16
    for (int k = 0; k < Dd; k++) acc = fmaf(g_Vinv[d*Dd + k], B[k*Hd + h], acc);
    g_W[idx] = acc;
}

// ---------------- K3: features GEMM + transcendentals + chunk composites ------
__global__ void __launch_bounds__(512, 1)
k_features(const float* __restrict__ times,
           const int*   __restrict__ marks,
           const float* __restrict__ U,
           const float* __restrict__ gw,
           const float* __restrict__ gb,
           const float* __restrict__ llr,
           const float* __restrict__ lim,
           int nc) {
    __shared__ float sm[160*68];
    float* Us = sm;            // [64][68]
    float* Ws = sm + 64*68;    // [96][68]
    int tid = threadIdx.x;
    int n0  = blockIdx.x * 64;
    int tx = tid & 31, ty = tid >> 5;

    float acc[4][3];
    #pragma unroll
    for (int i = 0; i < 4; i++)
        #pragma unroll
        for (int j = 0; j < 3; j++) acc[i][j] = 0.f;

    for (int h0 = 0; h0 < Hd; h0 += 64) {
        __syncthreads();
        #pragma unroll
        for (int i = tid; i < 64*16; i += 512) {
            int r = i >> 4, c4 = i & 15;
            *(float4*)&Us[r*68 + c4*4] = *(const float4*)&U[(n0 + r)*Hd + h0 + c4*4];
        }
        #pragma unroll
        for (int i = tid; i < 96*16; i += 512) {
            int r = i >> 4, c4 = i & 15;
            const float* src = (r < 32) ? &gw[r*Hd + h0 + c4*4]
                                        : &g_W[(r-32)*Hd + h0 + c4*4];
            *(float4*)&Ws[r*68 + c4*4] = *(const float4*)src;
        }
        __syncthreads();
        #pragma unroll 8
        for (int h4 = 0; h4 < 64; h4 += 4) {
            float4 rv[4], cv[3];
            #pragma unroll
            for (int ri = 0; ri < 4; ri++)
                rv[ri] = *(const float4*)&Us[(ty*4 + ri)*68 + h4];
            #pragma unroll
            for (int ci = 0; ci < 3; ci++)
                cv[ci] = *(const float4*)&Ws[(tx + 32*ci)*68 + h4];
            #pragma unroll
            for (int ri = 0; ri < 4; ri++)
                #pragma unroll
                for (int ci = 0; ci < 3; ci++) {
                    acc[ri][ci] = fmaf(rv[ri].x, cv[ci].x, acc[ri][ci]);
                    acc[ri][ci] = fmaf(rv[ri].y, cv[ci].y, acc[ri][ci]);
                    acc[ri][ci] = fmaf(rv[ri].z, cv[ci].z, acc[ri][ci]);
                    acc[ri][ci] = fmaf(rv[ri].w, cv[ci].w, acc[ri][ci]);
                }
        }
    }

    __syncthreads();
    float* M = sm;  // 64 x 97 (cols 0..31 gate_pre, 32..95 w)
    #pragma unroll
    for (int ri = 0; ri < 4; ri++)
        #pragma unroll
        for (int ci = 0; ci < 3; ci++)
            M[(ty*4 + ri)*97 + (tx + 32*ci)] = acc[ri][ci];
    __syncthreads();

    {
        int p  = tid & 31;
        int r0 = tid >> 5;
        float spl = softplus_fast(llr[p]);
        float im  = lim[p];
        float gbp = gb[p];
        #pragma unroll
        for (int q = 0; q < 4; q++) {
            int r = r0 + q*16;
            int n = n0 + r;
            float tn = times[n];
            float dt = tn - ((n > 0) ? times[n-1] : 0.f);
            float gate = softplus_fast(M[r*97 + p] + gbp);
            float re   = -spl * gate;
            float er = __expf(re * dt);
            float th = im * dt;
            float a = er * __cosf(th);
            float c = er * __sinf(th);
            float denom = re*re + im*im;
            float nr = a - 1.f, ni = c;
            float inv_d = __fdividef(1.f, denom + 1e-12f);
            float qr = (nr*re + ni*im) * inv_d;
            float qi = (ni*re - nr*im) * inv_d;
            if (denom < 1e-8f) { qr = dt; qi = 0.f; }
            float wre = M[r*97 + 32 + 2*p];
            float wim = M[r*97 + 33 + 2*p];
            float pos = (dt > 0.f) ? 1.f : 0.f;
            int   mk  = marks[n];
            float ure = (qr*wre - qi*wim) * pos + g_G[(2*p)*Kd + mk];
            float uim = (qr*wim + qi*wre) * pos + g_G[(2*p+1)*Kd + mk];
            g_e[n*Pd + p] = make_float2(a, c);
            g_u[n*Pd + p] = make_float2(ure, uim);
        }
    }

    __syncthreads();
    int w = tid >> 5, lane = tid & 31;
    if (w < 8) {
        int cglob = blockIdx.x * 8 + w;
        int base  = n0 + w * 8;
        float2 Ecomp = make_float2(1.f, 0.f);
        float2 Ucomp = make_float2(0.f, 0.f);
        #pragma unroll
        for (int i = 0; i < CL; i++) {
            float2 e = g_e[(base + i)*Pd + lane];
            float2 u = g_u[(base + i)*Pd + lane];
            Ucomp = cmul(e, Ucomp); Ucomp.x += u.x; Ucomp.y += u.y;
            Ecomp = cmul(e, Ecomp);
        }
        g_Ec[lane*nc + cglob] = Ecomp;   // [p][c]
        g_Uc[lane*nc + cglob] = Ucomp;
    }
}

// ---------------- K4: hybrid scan (warp scan + aggregate scan), 1 block/p -----
// Affine composition: (E2,U2) after (E1,U1) => (E2*E1, E2*U1 + U2).
__global__ void __launch_bounds__(1024, 1) k_scan(int nc) {
    __shared__ float4 wagg[32];     // per-warp aggregates
    __shared__ float4 buf[1024];    // inclusive prefixes
    int p = blockIdx.x;
    int c = threadIdx.x;
    int lane = c & 31, wid = c >> 5;

    float2 E = make_float2(1.f, 0.f);
    float2 Uv = make_float2(0.f, 0.f);
    if (c < nc) { E = g_Ec[p*nc + c]; Uv = g_Uc[p*nc + c]; }

    // warp-inclusive scan
    #pragma unroll
    for (int off = 1; off <= 16; off <<= 1) {
        float Ex = __shfl_up_sync(0xFFFFFFFFu, E.x, off);
        float Ey = __shfl_up_sync(0xFFFFFFFFu, E.y, off);
        float Ux = __shfl_up_sync(0xFFFFFFFFu, Uv.x, off);
        float Uy = __shfl_up_sync(0xFFFFFFFFu, Uv.y, off);
        if (lane >= off) {
            float2 t = cmul(E, make_float2(Ux, Uy));
            Uv.x += t.x; Uv.y += t.y;
            E = cmul(E, make_float2(Ex, Ey));
        }
    }
    if (lane == 31) wagg[wid] = make_float4(E.x, E.y, Uv.x, Uv.y);
    __syncthreads();

    // warp 0 scans the 32 warp aggregates (inclusive)
    if (wid == 0) {
        float4 a4 = wagg[lane];
        float2 We = make_float2(a4.x, a4.y);
        float2 Wu = make_float2(a4.z, a4.w);
        #pragma unroll
        for (int off = 1; off <= 16; off <<= 1) {
            float Ex = __shfl_up_sync(0xFFFFFFFFu, We.x, off);
            float Ey = __shfl_up_sync(0xFFFFFFFFu, We.y, off);
            float Ux = __shfl_up_sync(0xFFFFFFFFu, Wu.x, off);
            float Uy = __shfl_up_sync(0xFFFFFFFFu, Wu.y, off);
            if (lane >= off) {
                float2 t = cmul(We, make_float2(Ux, Uy));
                Wu.x += t.x; Wu.y += t.y;
                We = cmul(We, make_float2(Ex, Ey));
            }
        }
        wagg[lane] = make_float4(We.x, We.y, Wu.x, Wu.y);
    }
    __syncthreads();

    // compose local prefix after exclusive warp-aggregate prefix
    if (wid > 0) {
        float4 pr = wagg[wid - 1];
        float2 t = cmul(E, make_float2(pr.z, pr.w));
        Uv.x += t.x; Uv.y += t.y;
        E = cmul(E, make_float2(pr.x, pr.y));
    }
    buf[c] = make_float4(E.x, E.y, Uv.x, Uv.y);
    __syncthreads();

    // carry into chunk c = inclusive_prefix(c-1) applied to y0
    float2 y0p = make_float2(g_y0[2*p], g_y0[2*p + 1]);
    float2 carry;
    if (c == 0) carry = y0p;
    else {
        float4 pr = buf[c - 1];
        carry = cmul(make_float2(pr.x, pr.y), y0p);
        carry.x += pr.z; carry.y += pr.w;
    }
    if (c < nc) g_carry[c*Pd + p] = carry;
}

// ---------------- K5: fused replay + output ----------------------------------
__global__ void k_replay_out(const float* __restrict__ Vmat,
                             const int*   __restrict__ marks,
                             float* __restrict__ out, int Nn) {
    __shared__ float Vs[Dd*68];
    __shared__ float Ys[64*68];
    __shared__ int   mks[64];
    int tid = threadIdx.x;
    int n0 = blockIdx.x * 64;

    for (int i = tid; i < Dd*Dd; i += 256) {
        int r = i >> 6, cc = i & 63;
        Vs[r*68 + cc] = Vmat[i];
    }
    if (tid < 64) mks[tid] = marks[n0 + tid];

    int w = tid >> 5, lane = tid & 31;
    {
        int chunk = blockIdx.x * 8 + w;
        int base  = n0 + w * 8;
        float2 z = g_carry[chunk*Pd + lane];
        #pragma unroll
        for (int i = 0; i < CL; i++) {
            float2 e = g_e[(base + i)*Pd + lane];
            float2 u = g_u[(base + i)*Pd + lane];
            z = cmul(e, z); z.x += u.x; z.y += u.y;
            Ys[(w*8 + i)*68 + 2*lane]     = z.x;
            Ys[(w*8 + i)*68 + 2*lane + 1] = z.y;
        }
    }
    __syncthreads();

    int i  = tid & 63;
    int rq = tid >> 6;
    const float4* Vr = (const float4*)&Vs[i*68];
    #pragma unroll
    for (int g = 0; g < 16; g++) {
        int row = g*4 + rq;
        const float4* Yr = (const float4*)&Ys[row*68];
        float acc = 0.f;
        #pragma unroll
        for (int k4 = 0; k4 < 16; k4++) {
            float4 v = Vr[k4];
            float4 y = Yr[k4];
            acc = fmaf(v.x, y.x, acc);
            acc = fmaf(v.y, y.y, acc);
            acc = fmaf(v.z, y.z, acc);
            acc = fmaf(v.w, y.w, acc);
        }
        int n  = n0 + row;
        int mk = mks[row];
        out[n*Dd + i]         = acc;
        out[Nn*Dd + n*Dd + i] = acc - g_EA[i*Kd + mk];
    }
}

// ---------------- launch ------------------------------------------------------
extern "C" void kernel_launch(void* const* d_in, const int* in_sizes, int n_in,
                              void* d_out, int out_size) {
    const float* times = (const float*)d_in[0];
    const int*   marks = (const int*)  d_in[1];
    const float* u     = (const float*)d_in[2];
    const float* llr   = (const float*)d_in[3];
    const float* lim   = (const float*)d_in[4];
    const float* V     = (const float*)d_in[5];
    const float* B     = (const float*)d_in[6];
    const float* E     = (const float*)d_in[7];
    const float* alpha = (const float*)d_in[8];
    const float* gw    = (const float*)d_in[9];
    const float* gb    = (const float*)d_in[10];
    const float* x0    = (const float*)d_in[11];
    float* out = (float*)d_out;

    int Nn = in_sizes[0];          // 8192
    int nc = Nn / CL;              // 1024 chunks

    k_inv    <<<1, 512>>>(V);
    k_setupEA<<<1, 256>>>(E, alpha, x0);
    k_setupW <<<64, 512>>>(B);
    k_features<<<Nn/64, 512>>>(times, marks, u, gw, gb, llr, lim, nc);  // launch #4 -> profiled
    k_scan   <<<Pd, 1024>>>(nc);
    k_replay_out<<<Nn/64, 256>>>(V, marks, out, Nn);
}